// round 13
// baseline (speedup 1.0000x reference)
#include <cuda_runtime.h>
#include <math.h>

#define SQ   4096
#define L    4097
#define H    32
#define NH   8
#define HD   4
#define FF   2048
#define NL   6
#define EPSF 1e-5f
// 0.5 * log2(e): fold 1/sqrt(HD)=0.5 and the exp->exp2 conversion into Q
#define QSCALE 0.72134752044448170368f
#define KSPLIT 32
#define CHUNK  130          // even: pair-aligned chunks; 32*130=4160>=4097
#define PAIRS  2049         // ceil(L/2)
#define QT     384          // queries per block (3 per thread)
#define FSPL   4            // FF split factor
#define FCH    128          // f-chunk per smem stage
#define W2PAD  132          // W2s row stride (floats): 528B, 16B-aligned

typedef unsigned long long ull;

// ---- persistent scratch (no allocations allowed) ----
__device__ float  g_X[L * H];             // activations [L][32]
__device__ float4 g_Q[NH * L];            // [h][pos] head-major, pre-scaled by QSCALE
__device__ float  g_K2[NH * PAIRS * 8];   // pair-interleaved: [h][pair][d*2+j]
__device__ float  g_V2[NH * PAIRS * 8];
__device__ float4 g_P[KSPLIT * NH * L];   // attention partial sum(p*v) [c][h][q]
__device__ float  g_PL[KSPLIT * NH * L];  // attention partial sum(p)   [c][h][q]
__device__ float  g_Y[FSPL * L * H];      // FF partial outputs [s][r][h]

__device__ __forceinline__ float warp_sum(float v) {
#pragma unroll
    for (int o = 16; o; o >>= 1) v += __shfl_xor_sync(0xffffffffu, v, o);
    return v;
}

// ---- packed f32x2 helpers (ptxas never auto-fuses; must be PTX) ----
__device__ __forceinline__ ull pk2(float a, float b) {
    ull r;
    asm("mov.b64 %0,{%1,%2};" : "=l"(r) : "f"(a), "f"(b));
    return r;
}
__device__ __forceinline__ void upk2(ull v, float& a, float& b) {
    asm("mov.b64 {%0,%1},%2;" : "=f"(a), "=f"(b) : "l"(v));
}
__device__ __forceinline__ ull fma2_(ull a, ull b, ull c) {
    ull r;
    asm("fma.rn.f32x2 %0,%1,%2,%3;" : "=l"(r) : "l"(a), "l"(b), "l"(c));
    return r;
}
__device__ __forceinline__ ull mul2_(ull a, ull b) {
    ull r;
    asm("mul.rn.f32x2 %0,%1,%2;" : "=l"(r) : "l"(a), "l"(b));
    return r;
}
__device__ __forceinline__ ull add2_(ull a, ull b) {
    ull r;
    asm("add.rn.f32x2 %0,%1,%2;" : "=l"(r) : "l"(a), "l"(b));
    return r;
}
__device__ __forceinline__ float ex2(float x) {
    float r;
    asm("ex2.approx.f32 %0,%1;" : "=f"(r) : "f"(x));
    return r;
}

// ---- embedding: linear+relu + sinusoidal PE, CLS row = -1 ----
__global__ void k_embed(const float* __restrict__ data,
                        const float* __restrict__ lw,
                        const float* __restrict__ lb) {
    __shared__ float divs[16];
    if (threadIdx.x < 16) {
        // match JAX: f32 arg = f32(2j) * f32(-ln(10000)/32), then exp (corr. rounded)
        float arg = (float)(2 * threadIdx.x) * (float)(-0.28782313662425575);
        divs[threadIdx.x] = (float)exp((double)arg);
    }
    __syncthreads();
    int t = blockIdx.x * blockDim.x + threadIdx.x;
    if (t >= L) return;
    if (t == 0) {
#pragma unroll
        for (int h = 0; h < H; h++) g_X[h] = -1.0f;
        return;
    }
    int s = t - 1;
    float ts = data[s * 3 + 0];
    float f1 = data[s * 3 + 1];
    float f2 = data[s * 3 + 2];
    int idx = (int)(ts / 100.0f);
    float fidx = (float)idx;
#pragma unroll
    for (int j = 0; j < 16; j++) {
        float ang = fidx * divs[j];
        float sn, cs;
        sincosf(ang, &sn, &cs);
        float v0 = fmaxf(f1 * lw[4 * j + 0] + f2 * lw[4 * j + 1] + lb[2 * j], 0.f) + sn;
        float v1 = fmaxf(f1 * lw[4 * j + 2] + f2 * lw[4 * j + 3] + lb[2 * j + 1], 0.f) + cs;
        g_X[t * H + 2 * j]     = v0;
        g_X[t * H + 2 * j + 1] = v1;
    }
}

// ---- shared qkv math: one warp per row, xv = this lane's x value ----
__device__ __forceinline__ void qkv_row(float xv, int gw, int lane,
                                        const float* Ws, const float* Bs) {
    float aq = Bs[lane], ak = Bs[32 + lane], av = Bs[64 + lane];
    const float* wq = &Ws[lane * 33];
    const float* wk = &Ws[(32 + lane) * 33];
    const float* wv = &Ws[(64 + lane) * 33];
#pragma unroll
    for (int i = 0; i < 32; i++) {
        float xi = __shfl_sync(0xffffffffu, xv, i);
        aq = fmaf(xi, wq[i], aq);
        ak = fmaf(xi, wk[i], ak);
        av = fmaf(xi, wv[i], av);
    }
    int h = lane >> 2, d = lane & 3;
    ((float*)g_Q)[(h * L + gw) * 4 + d] = aq * QSCALE;
    int ob = (h * PAIRS + (gw >> 1)) * 8 + d * 2 + (gw & 1);
    g_K2[ob] = ak;
    g_V2[ob] = av;
}

// ---- QKV projection (layer 0) ----
__global__ __launch_bounds__(256) void k_qkv(const float* __restrict__ w,
                                             const float* __restrict__ b) {
    __shared__ float Ws[96 * 33];
    __shared__ float Bs[96];
    for (int e = threadIdx.x; e < 96 * 32; e += 256)
        Ws[(e >> 5) * 33 + (e & 31)] = w[e];
    if (threadIdx.x < 96) Bs[threadIdx.x] = b[threadIdx.x];
    __syncthreads();
    int gw = (blockIdx.x * 256 + threadIdx.x) >> 5;
    int lane = threadIdx.x & 31;
    if (gw >= L) return;
    qkv_row(g_X[gw * H + lane], gw, lane, Ws, Bs);
}

// ---- attention: split-K, 3 queries/thread, 2-key packed f32x2 math ----
// grid = (ceil(L/QT), NH, KSPLIT), block = 128
__global__ __launch_bounds__(128) void k_attn() {
    __shared__ float4 Ks[66 * 2], Vs[66 * 2];  // up to 65 pairs, 2 float4 each
    int h = blockIdx.y;
    int c = blockIdx.z;
    int k0 = c * CHUNK;
    int nk = min(CHUNK, L - k0);
    int np = (nk + 1) >> 1;           // pairs staged (incl. odd tail's pair)
    int p0 = k0 >> 1;                 // k0 even by construction
    const float4* srcK = (const float4*)(g_K2 + (h * PAIRS + p0) * 8);
    const float4* srcV = (const float4*)(g_V2 + (h * PAIRS + p0) * 8);
    for (int j = threadIdx.x; j < np * 2; j += 128) {
        Ks[j] = srcK[j];
        Vs[j] = srcV[j];
    }
    int q0 = blockIdx.x * QT + threadIdx.x;
    int q1 = q0 + 128;
    int q2 = q0 + 256;
    float4 qa = make_float4(0.f, 0.f, 0.f, 0.f);
    float4 qb = make_float4(0.f, 0.f, 0.f, 0.f);
    float4 qc = make_float4(0.f, 0.f, 0.f, 0.f);
    if (q0 < L) qa = g_Q[h * L + q0];
    if (q1 < L) qb = g_Q[h * L + q1];
    if (q2 < L) qc = g_Q[h * L + q2];
    ull qx0 = pk2(qa.x, qa.x), qy0 = pk2(qa.y, qa.y);
    ull qz0 = pk2(qa.z, qa.z), qw0 = pk2(qa.w, qa.w);
    ull qx1 = pk2(qb.x, qb.x), qy1 = pk2(qb.y, qb.y);
    ull qz1 = pk2(qb.z, qb.z), qw1 = pk2(qb.w, qb.w);
    ull qx2 = pk2(qc.x, qc.x), qy2 = pk2(qc.y, qc.y);
    ull qz2 = pk2(qc.z, qc.z), qw2 = pk2(qc.w, qc.w);
    ull z = 0;
    ull a0x = z, a0y = z, a0z = z, a0w = z;
    ull a1x = z, a1y = z, a1z = z, a1w = z;
    ull a2x = z, a2y = z, a2z = z, a2w = z;
    ull sA = z, sB = z, sC = z;
    __syncthreads();
    const ulonglong2* Kp = (const ulonglong2*)Ks;
    const ulonglong2* Vp = (const ulonglong2*)Vs;
    int npair = nk >> 1;
#pragma unroll 4
    for (int p = 0; p < npair; p++) {
        ulonglong2 kxy = Kp[2 * p];       // ({x0,x1},{y0,y1})
        ulonglong2 kzw = Kp[2 * p + 1];   // ({z0,z1},{w0,w1})
        ulonglong2 vxy = Vp[2 * p];
        ulonglong2 vzw = Vp[2 * p + 1];
        ull t0 = fma2_(qz0, kzw.x, mul2_(qw0, kzw.y));
        t0 = fma2_(qx0, kxy.x, fma2_(qy0, kxy.y, t0));
        ull t1 = fma2_(qz1, kzw.x, mul2_(qw1, kzw.y));
        t1 = fma2_(qx1, kxy.x, fma2_(qy1, kxy.y, t1));
        ull t2 = fma2_(qz2, kzw.x, mul2_(qw2, kzw.y));
        t2 = fma2_(qx2, kxy.x, fma2_(qy2, kxy.y, t2));
        float s0a, s0b, s1a, s1b, s2a, s2b;
        upk2(t0, s0a, s0b);
        upk2(t1, s1a, s1b);
        upk2(t2, s2a, s2b);
        float p0a = ex2(s0a), p0b = ex2(s0b);
        float p1a = ex2(s1a), p1b = ex2(s1b);
        float p2a = ex2(s2a), p2b = ex2(s2b);
        ull pp0 = pk2(p0a, p0b);
        ull pp1 = pk2(p1a, p1b);
        ull pp2 = pk2(p2a, p2b);
        sA = add2_(sA, pp0);
        sB = add2_(sB, pp1);
        sC = add2_(sC, pp2);
        a0x = fma2_(pp0, vxy.x, a0x);
        a0y = fma2_(pp0, vxy.y, a0y);
        a0z = fma2_(pp0, vzw.x, a0z);
        a0w = fma2_(pp0, vzw.y, a0w);
        a1x = fma2_(pp1, vxy.x, a1x);
        a1y = fma2_(pp1, vxy.y, a1y);
        a1z = fma2_(pp1, vzw.x, a1z);
        a1w = fma2_(pp1, vzw.y, a1w);
        a2x = fma2_(pp2, vxy.x, a2x);
        a2y = fma2_(pp2, vxy.y, a2y);
        a2z = fma2_(pp2, vzw.x, a2z);
        a2w = fma2_(pp2, vzw.y, a2w);
    }
    float sa, sb, sc;
    {
        float lo, hi;
        upk2(sA, lo, hi); sa = lo + hi;
        upk2(sB, lo, hi); sb = lo + hi;
        upk2(sC, lo, hi); sc = lo + hi;
    }
    float e0x = 0.f, e0y = 0.f, e0z = 0.f, e0w = 0.f;
    float e1x = 0.f, e1y = 0.f, e1z = 0.f, e1w = 0.f;
    float e2x = 0.f, e2y = 0.f, e2z = 0.f, e2w = 0.f;
    if (nk & 1) {   // scalar epilogue for the odd tail key (j=0 of last pair)
        const float* Kf = (const float*)Ks;
        const float* Vf = (const float*)Vs;
        int base = (nk >> 1) * 8;
        float kx = Kf[base + 0], ky = Kf[base + 2], kz = Kf[base + 4], kw = Kf[base + 6];
        float vx = Vf[base + 0], vy = Vf[base + 2], vz = Vf[base + 4], vw = Vf[base + 6];
        float s0 = fmaf(qa.x, kx, fmaf(qa.y, ky, fmaf(qa.z, kz, qa.w * kw)));
        float s1 = fmaf(qb.x, kx, fmaf(qb.y, ky, fmaf(qb.z, kz, qb.w * kw)));
        float s2 = fmaf(qc.x, kx, fmaf(qc.y, ky, fmaf(qc.z, kz, qc.w * kw)));
        float p0 = ex2(s0), p1 = ex2(s1), p2 = ex2(s2);
        sa += p0; sb += p1; sc += p2;
        e0x = p0 * vx; e0y = p0 * vy; e0z = p0 * vz; e0w = p0 * vw;
        e1x = p1 * vx; e1y = p1 * vy; e1z = p1 * vz; e1w = p1 * vw;
        e2x = p2 * vx; e2y = p2 * vy; e2z = p2 * vz; e2w = p2 * vw;
    }
    int base = (c * NH + h) * L;
    if (q0 < L) {
        float lo, hi;
        float4 r;
        upk2(a0x, lo, hi); r.x = lo + hi + e0x;
        upk2(a0y, lo, hi); r.y = lo + hi + e0y;
        upk2(a0z, lo, hi); r.z = lo + hi + e0z;
        upk2(a0w, lo, hi); r.w = lo + hi + e0w;
        g_P[base + q0] = r;
        g_PL[base + q0] = sa;
    }
    if (q1 < L) {
        float lo, hi;
        float4 r;
        upk2(a1x, lo, hi); r.x = lo + hi + e1x;
        upk2(a1y, lo, hi); r.y = lo + hi + e1y;
        upk2(a1z, lo, hi); r.z = lo + hi + e1z;
        upk2(a1w, lo, hi); r.w = lo + hi + e1w;
        g_P[base + q1] = r;
        g_PL[base + q1] = sb;
    }
    if (q2 < L) {
        float lo, hi;
        float4 r;
        upk2(a2x, lo, hi); r.x = lo + hi + e2x;
        upk2(a2y, lo, hi); r.y = lo + hi + e2y;
        upk2(a2z, lo, hi); r.z = lo + hi + e2z;
        upk2(a2w, lo, hi); r.w = lo + hi + e2w;
        g_P[base + q2] = r;
        g_PL[base + q2] = sc;
    }
}

// ---- partial-combine + out-proj + residual + LN1 ----
// one ROW per 128-thread block; 4 warps split the c-dim (8 chunks each),
// smem-reduce, warp 0 does projection + LN. Sum order == sequential c.
__global__ __launch_bounds__(128) void k_aoln(const float* __restrict__ w,
                                              const float* __restrict__ b,
                                              const float* __restrict__ g1,
                                              const float* __restrict__ b1) {
    __shared__ float Ws[32 * 33];
    __shared__ float Bs[32], Gs[32], B1s[32];
    __shared__ float Os[4][32], Ls[4][32];
    for (int e = threadIdx.x; e < 1024; e += 128)
        Ws[(e >> 5) * 33 + (e & 31)] = w[e];
    if (threadIdx.x < 32) {
        Bs[threadIdx.x] = b[threadIdx.x];
        Gs[threadIdx.x] = g1[threadIdx.x];
        B1s[threadIdx.x] = b1[threadIdx.x];
    }
    int r = blockIdx.x;
    int wp = threadIdx.x >> 5;
    int lane = threadIdx.x & 31;
    int h4 = lane >> 2, d = lane & 3;
    float o = 0.f, ls = 0.f;
#pragma unroll
    for (int cc = 0; cc < KSPLIT / 4; cc++) {
        int c = wp * (KSPLIT / 4) + cc;
        int idx = (c * NH + h4) * L + r;
        o += ((const float*)g_P)[idx * 4 + d];
        ls += g_PL[idx];
    }
    Os[wp][lane] = o;
    Ls[wp][lane] = ls;
    __syncthreads();
    if (wp != 0) return;
    o  = Os[0][lane] + Os[1][lane] + Os[2][lane] + Os[3][lane];
    ls = Ls[0][lane] + Ls[1][lane] + Ls[2][lane] + Ls[3][lane];
    float ov = o / ls;
    float acc = Bs[lane];
    const float* wr = &Ws[lane * 33];
#pragma unroll
    for (int i = 0; i < 32; i++) {
        float oi = __shfl_sync(0xffffffffu, ov, i);
        acc = fmaf(oi, wr[i], acc);
    }
    float xv = g_X[r * H + lane] + acc;
    float m = warp_sum(xv) * (1.0f / 32.0f);
    float dd = xv - m;
    float var = warp_sum(dd * dd) * (1.0f / 32.0f);
    float y = dd * rsqrtf(var + EPSF);
    g_X[r * H + lane] = fmaf(y, Gs[lane], B1s[lane]);
}

// ---- fused FF (packed f32x2): relu(X*W1^T) chunk -> W2 partial ----
// grid = (ceil(L/32), FSPL), block = 256
__global__ __launch_bounds__(256) void k_ff(const float* __restrict__ w1,
                                            const float* __restrict__ b1,
                                            const float* __restrict__ w2) {
    __shared__ float4 Xs[32 * 8];        // [r][c4]   4KB
    __shared__ float  Fs[32 * FCH];      // [r][kk]   16KB
    __shared__ float  W2s[32 * W2PAD];   // [h][kk]   16.9KB, stride 132
    int r0 = blockIdx.x * 32;
    int s  = blockIdx.y;
    {
        int r = threadIdx.x >> 3, c = threadIdx.x & 7;
        float4 v = make_float4(0.f, 0.f, 0.f, 0.f);
        if (r0 + r < L) v = ((const float4*)g_X)[(r0 + r) * 8 + c];
        Xs[threadIdx.x] = v;
    }
    int h  = threadIdx.x & 31;
    int rs = threadIdx.x >> 5;        // warp id -> row group (4 rows)
    int fl = threadIdx.x & 127;       // f column within chunk
    int rh = (threadIdx.x >> 7) * 16; // row half for ff1 stage (0 or 16)
    ull accp0 = 0, accp1 = 0, accp2 = 0, accp3 = 0;  // packed over k-parity
#pragma unroll 1
    for (int ch = 0; ch < (FF / FSPL) / FCH; ch++) {   // 4 chunks of 128 f
        int fbase = s * (FF / FSPL) + ch * FCH;
        __syncthreads();   // prev chunk's readers done; Xs ready on first iter
        {   // stage W2s[h][kk] from w2 (layout [h][ff] already!): coalesced
#pragma unroll
            for (int j = 0; j < 4; j++) {
                int t = threadIdx.x + 256 * j;
                int hh = t >> 5, k4 = (t & 31) * 4;
                *(float4*)(W2s + hh * W2PAD + k4) =
                    *(const float4*)(w2 + hh * FF + fbase + k4);
            }
        }
        {   // ff1: two threads per f column, 16 rows each; K-packed (full 32 k)
            int f = fbase + fl;
            const ulonglong2* wp = (const ulonglong2*)(w1 + f * 32);
            ulonglong2 wv[8];
#pragma unroll
            for (int j = 0; j < 8; j++) wv[j] = wp[j];
            float bias = b1[f];
            for (int rr = 0; rr < 16; rr++) {
                int r = rh + rr;
                const ulonglong2* xp = (const ulonglong2*)&Xs[r * 8];
                ull a = mul2_(xp[0].x, wv[0].x);
                a = fma2_(xp[0].y, wv[0].y, a);
#pragma unroll
                for (int j = 1; j < 8; j++) {
                    ulonglong2 xj = xp[j];
                    a = fma2_(xj.x, wv[j].x, a);
                    a = fma2_(xj.y, wv[j].y, a);
                }
                float lo, hi;
                upk2(a, lo, hi);
                Fs[r * FCH + fl] = fmaxf(lo + hi + bias, 0.f);
            }
        }
        __syncthreads();
        // ff2 partial: thread (rs,h) rows rs*4..+3, packed over kk pairs
        const ulonglong2* wrow = (const ulonglong2*)(W2s + h * W2PAD);
        const ulonglong2* f0p = (const ulonglong2*)&Fs[(rs * 4 + 0) * FCH];
        const ulonglong2* f1p = (const ulonglong2*)&Fs[(rs * 4 + 1) * FCH];
        const ulonglong2* f2p = (const ulonglong2*)&Fs[(rs * 4 + 2) * FCH];
        const ulonglong2* f3p = (const ulonglong2*)&Fs[(rs * 4 + 3) * FCH];
#pragma unroll 8
        for (int k4 = 0; k4 < FCH / 4; k4++) {
            ulonglong2 ww = wrow[k4];
            ulonglong2 f0 = f0p[k4];
            ulonglong2 f1 = f1p[k4];
            ulonglong2 f2 = f2p[k4];
            ulonglong2 f3 = f3p[k4];
            accp0 = fma2_(f0.x, ww.x, accp0);
            accp0 = fma2_(f0.y, ww.y, accp0);
            accp1 = fma2_(f1.x, ww.x, accp1);
            accp1 = fma2_(f1.y, ww.y, accp1);
            accp2 = fma2_(f2.x, ww.x, accp2);
            accp2 = fma2_(f2.y, ww.y, accp2);
            accp3 = fma2_(f3.x, ww.x, accp3);
            accp3 = fma2_(f3.y, ww.y, accp3);
        }
    }
    ull accs[4] = {accp0, accp1, accp2, accp3};
#pragma unroll
    for (int j = 0; j < 4; j++) {
        int r = r0 + rs * 4 + j;
        if (r < L) {
            float lo, hi;
            upk2(accs[j], lo, hi);
            g_Y[(s * L + r) * H + h] = lo + hi;
        }
    }
}

// ---- FF partial-combine + bias + residual + LN2 (+ optional fused qkv) ----
__device__ __forceinline__ float ln2_row(int r, int h,
                                         const float* __restrict__ b2,
                                         const float* __restrict__ g2,
                                         const float* __restrict__ b2ln) {
    float y = b2[h];
#pragma unroll
    for (int s = 0; s < FSPL; s++) y += g_Y[(s * L + r) * H + h];
    float val = g_X[r * H + h] + y;
    float m = warp_sum(val) * (1.0f / 32.0f);
    float d = val - m;
    float var = warp_sum(d * d) * (1.0f / 32.0f);
    float yn = d * rsqrtf(var + EPSF);
    float xn = fmaf(yn, g2[h], b2ln[h]);
    g_X[r * H + h] = xn;
    return xn;
}

__global__ __launch_bounds__(256) void k_ln2(const float* __restrict__ b2,
                                             const float* __restrict__ g2,
                                             const float* __restrict__ b2ln) {
    int r = (blockIdx.x * 256 + threadIdx.x) >> 5;
    int h = threadIdx.x & 31;
    if (r >= L) return;
    ln2_row(r, h, b2, g2, b2ln);
}

// ln2 of layer l fused with qkv of layer l+1
__global__ __launch_bounds__(256) void k_ln2qkv(const float* __restrict__ b2,
                                                const float* __restrict__ g2,
                                                const float* __restrict__ b2ln,
                                                const float* __restrict__ wq,
                                                const float* __restrict__ bq) {
    __shared__ float Ws[96 * 33];
    __shared__ float Bs[96];
    for (int e = threadIdx.x; e < 96 * 32; e += 256)
        Ws[(e >> 5) * 33 + (e & 31)] = wq[e];
    if (threadIdx.x < 96) Bs[threadIdx.x] = bq[threadIdx.x];
    __syncthreads();
    int r = (blockIdx.x * 256 + threadIdx.x) >> 5;
    int lane = threadIdx.x & 31;
    if (r >= L) return;
    float xn = ln2_row(r, lane, b2, g2, b2ln);
    qkv_row(xn, r, lane, Ws, Bs);
}

// ---- classifier head ----
__global__ void k_head(const float* __restrict__ cw,
                       const float* __restrict__ cb,
                       float* __restrict__ out) {
    int lane = threadIdx.x;
    float v = g_X[lane] * cw[lane];
    v = warp_sum(v);
    if (lane == 0) {
        float z = v + cb[0];
        out[0] = 1.0f / (1.0f + expf(-z));
    }
}

extern "C" void kernel_launch(void* const* d_in, const int* in_sizes, int n_in,
                              void* d_out, int out_size) {
    const float* data  = (const float*)d_in[0];
    const float* lin_w = (const float*)d_in[1];
    const float* lin_b = (const float*)d_in[2];
    const float* qkv_w = (const float*)d_in[3];
    const float* qkv_b = (const float*)d_in[4];
    const float* out_w = (const float*)d_in[5];
    const float* out_b = (const float*)d_in[6];
    const float* ln1_g = (const float*)d_in[7];
    const float* ln1_b = (const float*)d_in[8];
    const float* ff1_w = (const float*)d_in[9];
    const float* ff1_b = (const float*)d_in[10];
    const float* ff2_w = (const float*)d_in[11];
    const float* ff2_b = (const float*)d_in[12];
    const float* ln2_g = (const float*)d_in[13];
    const float* ln2_b = (const float*)d_in[14];
    const float* cls_w = (const float*)d_in[15];
    const float* cls_b = (const float*)d_in[16];
    float* out = (float*)d_out;

    k_embed<<<(L + 255) / 256, 256>>>(data, lin_w, lin_b);
    k_qkv<<<(L + 7) / 8, 256>>>(qkv_w, qkv_b);
    for (int l = 0; l < NL; l++) {
        k_attn<<<dim3((L + QT - 1) / QT, NH, KSPLIT), 128>>>();
        k_aoln<<<L, 128>>>(out_w + l * H * H, out_b + l * H,
                           ln1_g + l * H, ln1_b + l * H);
        k_ff<<<dim3((L + 31) / 32, FSPL), 256>>>(ff1_w + l * FF * H, ff1_b + l * FF,
                                                 ff2_w + l * H * FF);
        if (l < NL - 1) {
            k_ln2qkv<<<(L + 7) / 8, 256>>>(ff2_b + l * H, ln2_g + l * H, ln2_b + l * H,
                                           qkv_w + (l + 1) * 96 * H,
                                           qkv_b + (l + 1) * 96);
        } else {
            k_ln2<<<(L + 7) / 8, 256>>>(ff2_b + l * H, ln2_g + l * H, ln2_b + l * H);
        }
    }
    k_head<<<1, 32>>>(cls_w, cls_b, out);
}

// round 15
// speedup vs baseline: 1.1001x; 1.1001x over previous
#include <cuda_runtime.h>
#include <math.h>

#define SQ   4096
#define L    4097
#define H    32
#define NH   8
#define HD   4
#define FF   2048
#define NL   6
#define EPSF 1e-5f
// 0.5 * log2(e): fold 1/sqrt(HD)=0.5 and the exp->exp2 conversion into Q
#define QSCALE 0.72134752044448170368f
#define KSPLIT 32
#define CHUNK  130          // even: pair-aligned chunks; 32*130=4160>=4097
#define PAIRS  2049         // ceil(L/2)
#define QT     384          // queries per block (3 per thread)
#define FSPL   8            // FF split factor
#define FCH    128          // f-chunk per smem stage
#define W2PAD  132          // W2s row stride (floats): 528B, 16B-aligned

typedef unsigned long long ull;

// ---- persistent scratch (no allocations allowed) ----
__device__ float  g_X[L * H];             // activations [L][32]
__device__ float4 g_Q[NH * L];            // [h][pos] head-major, pre-scaled by QSCALE
__device__ float  g_K2[NH * PAIRS * 8];   // pair-interleaved: [h][pair][d*2+j]
__device__ float  g_V2[NH * PAIRS * 8];
__device__ float4 g_P[KSPLIT * NH * L];   // attention partial sum(p*v) [c][h][q]
__device__ float  g_PL[KSPLIT * NH * L];  // attention partial sum(p)   [c][h][q]
__device__ float  g_Y[FSPL * L * H];      // FF partial outputs [s][r][h]

__device__ __forceinline__ float warp_sum(float v) {
#pragma unroll
    for (int o = 16; o; o >>= 1) v += __shfl_xor_sync(0xffffffffu, v, o);
    return v;
}

// ---- packed f32x2 helpers (ptxas never auto-fuses; must be PTX) ----
__device__ __forceinline__ ull pk2(float a, float b) {
    ull r;
    asm("mov.b64 %0,{%1,%2};" : "=l"(r) : "f"(a), "f"(b));
    return r;
}
__device__ __forceinline__ void upk2(ull v, float& a, float& b) {
    asm("mov.b64 {%0,%1},%2;" : "=f"(a), "=f"(b) : "l"(v));
}
__device__ __forceinline__ ull fma2_(ull a, ull b, ull c) {
    ull r;
    asm("fma.rn.f32x2 %0,%1,%2,%3;" : "=l"(r) : "l"(a), "l"(b), "l"(c));
    return r;
}
__device__ __forceinline__ ull mul2_(ull a, ull b) {
    ull r;
    asm("mul.rn.f32x2 %0,%1,%2;" : "=l"(r) : "l"(a), "l"(b));
    return r;
}
__device__ __forceinline__ ull add2_(ull a, ull b) {
    ull r;
    asm("add.rn.f32x2 %0,%1,%2;" : "=l"(r) : "l"(a), "l"(b));
    return r;
}
__device__ __forceinline__ float ex2(float x) {
    float r;
    asm("ex2.approx.f32 %0,%1;" : "=f"(r) : "f"(x));
    return r;
}

// ---- embedding: linear+relu + sinusoidal PE, CLS row = -1 ----
__global__ void k_embed(const float* __restrict__ data,
                        const float* __restrict__ lw,
                        const float* __restrict__ lb) {
    __shared__ float divs[16];
    if (threadIdx.x < 16) {
        // match JAX: f32 arg = f32(2j) * f32(-ln(10000)/32), then exp (corr. rounded)
        float arg = (float)(2 * threadIdx.x) * (float)(-0.28782313662425575);
        divs[threadIdx.x] = (float)exp((double)arg);
    }
    __syncthreads();
    int t = blockIdx.x * blockDim.x + threadIdx.x;
    if (t >= L) return;
    if (t == 0) {
#pragma unroll
        for (int h = 0; h < H; h++) g_X[h] = -1.0f;
        return;
    }
    int s = t - 1;
    float ts = data[s * 3 + 0];
    float f1 = data[s * 3 + 1];
    float f2 = data[s * 3 + 2];
    int idx = (int)(ts / 100.0f);
    float fidx = (float)idx;
#pragma unroll
    for (int j = 0; j < 16; j++) {
        float ang = fidx * divs[j];
        float sn, cs;
        sincosf(ang, &sn, &cs);
        float v0 = fmaxf(f1 * lw[4 * j + 0] + f2 * lw[4 * j + 1] + lb[2 * j], 0.f) + sn;
        float v1 = fmaxf(f1 * lw[4 * j + 2] + f2 * lw[4 * j + 3] + lb[2 * j + 1], 0.f) + cs;
        g_X[t * H + 2 * j]     = v0;
        g_X[t * H + 2 * j + 1] = v1;
    }
}

// ---- shared qkv math: one warp per row, xv = this lane's x value ----
__device__ __forceinline__ void qkv_row(float xv, int gw, int lane,
                                        const float* Ws, const float* Bs) {
    float aq = Bs[lane], ak = Bs[32 + lane], av = Bs[64 + lane];
    const float* wq = &Ws[lane * 33];
    const float* wk = &Ws[(32 + lane) * 33];
    const float* wv = &Ws[(64 + lane) * 33];
#pragma unroll
    for (int i = 0; i < 32; i++) {
        float xi = __shfl_sync(0xffffffffu, xv, i);
        aq = fmaf(xi, wq[i], aq);
        ak = fmaf(xi, wk[i], ak);
        av = fmaf(xi, wv[i], av);
    }
    int h = lane >> 2, d = lane & 3;
    ((float*)g_Q)[(h * L + gw) * 4 + d] = aq * QSCALE;
    int ob = (h * PAIRS + (gw >> 1)) * 8 + d * 2 + (gw & 1);
    g_K2[ob] = ak;
    g_V2[ob] = av;
}

// ---- QKV projection (layer 0) ----
__global__ __launch_bounds__(256) void k_qkv(const float* __restrict__ w,
                                             const float* __restrict__ b) {
    __shared__ float Ws[96 * 33];
    __shared__ float Bs[96];
    for (int e = threadIdx.x; e < 96 * 32; e += 256)
        Ws[(e >> 5) * 33 + (e & 31)] = w[e];
    if (threadIdx.x < 96) Bs[threadIdx.x] = b[threadIdx.x];
    __syncthreads();
    int gw = (blockIdx.x * 256 + threadIdx.x) >> 5;
    int lane = threadIdx.x & 31;
    if (gw >= L) return;
    qkv_row(g_X[gw * H + lane], gw, lane, Ws, Bs);
}

// ---- attention: split-K, 3 queries/thread, 2-key packed f32x2 math ----
// grid = (ceil(L/QT), NH, KSPLIT), block = 128
__global__ __launch_bounds__(128) void k_attn() {
    __shared__ float4 Ks[66 * 2], Vs[66 * 2];  // up to 65 pairs, 2 float4 each
    int h = blockIdx.y;
    int c = blockIdx.z;
    int k0 = c * CHUNK;
    int nk = min(CHUNK, L - k0);
    int np = (nk + 1) >> 1;           // pairs staged (incl. odd tail's pair)
    int p0 = k0 >> 1;                 // k0 even by construction
    const float4* srcK = (const float4*)(g_K2 + (h * PAIRS + p0) * 8);
    const float4* srcV = (const float4*)(g_V2 + (h * PAIRS + p0) * 8);
    for (int j = threadIdx.x; j < np * 2; j += 128) {
        Ks[j] = srcK[j];
        Vs[j] = srcV[j];
    }
    int q0 = blockIdx.x * QT + threadIdx.x;
    int q1 = q0 + 128;
    int q2 = q0 + 256;
    float4 qa = make_float4(0.f, 0.f, 0.f, 0.f);
    float4 qb = make_float4(0.f, 0.f, 0.f, 0.f);
    float4 qc = make_float4(0.f, 0.f, 0.f, 0.f);
    if (q0 < L) qa = g_Q[h * L + q0];
    if (q1 < L) qb = g_Q[h * L + q1];
    if (q2 < L) qc = g_Q[h * L + q2];
    ull qx0 = pk2(qa.x, qa.x), qy0 = pk2(qa.y, qa.y);
    ull qz0 = pk2(qa.z, qa.z), qw0 = pk2(qa.w, qa.w);
    ull qx1 = pk2(qb.x, qb.x), qy1 = pk2(qb.y, qb.y);
    ull qz1 = pk2(qb.z, qb.z), qw1 = pk2(qb.w, qb.w);
    ull qx2 = pk2(qc.x, qc.x), qy2 = pk2(qc.y, qc.y);
    ull qz2 = pk2(qc.z, qc.z), qw2 = pk2(qc.w, qc.w);
    ull z = 0;
    ull a0x = z, a0y = z, a0z = z, a0w = z;
    ull a1x = z, a1y = z, a1z = z, a1w = z;
    ull a2x = z, a2y = z, a2z = z, a2w = z;
    ull sA = z, sB = z, sC = z;
    __syncthreads();
    const ulonglong2* Kp = (const ulonglong2*)Ks;
    const ulonglong2* Vp = (const ulonglong2*)Vs;
    int npair = nk >> 1;
#pragma unroll 4
    for (int p = 0; p < npair; p++) {
        ulonglong2 kxy = Kp[2 * p];       // ({x0,x1},{y0,y1})
        ulonglong2 kzw = Kp[2 * p + 1];   // ({z0,z1},{w0,w1})
        ulonglong2 vxy = Vp[2 * p];
        ulonglong2 vzw = Vp[2 * p + 1];
        ull t0 = fma2_(qz0, kzw.x, mul2_(qw0, kzw.y));
        t0 = fma2_(qx0, kxy.x, fma2_(qy0, kxy.y, t0));
        ull t1 = fma2_(qz1, kzw.x, mul2_(qw1, kzw.y));
        t1 = fma2_(qx1, kxy.x, fma2_(qy1, kxy.y, t1));
        ull t2 = fma2_(qz2, kzw.x, mul2_(qw2, kzw.y));
        t2 = fma2_(qx2, kxy.x, fma2_(qy2, kxy.y, t2));
        float s0a, s0b, s1a, s1b, s2a, s2b;
        upk2(t0, s0a, s0b);
        upk2(t1, s1a, s1b);
        upk2(t2, s2a, s2b);
        float p0a = ex2(s0a), p0b = ex2(s0b);
        float p1a = ex2(s1a), p1b = ex2(s1b);
        float p2a = ex2(s2a), p2b = ex2(s2b);
        ull pp0 = pk2(p0a, p0b);
        ull pp1 = pk2(p1a, p1b);
        ull pp2 = pk2(p2a, p2b);
        sA = add2_(sA, pp0);
        sB = add2_(sB, pp1);
        sC = add2_(sC, pp2);
        a0x = fma2_(pp0, vxy.x, a0x);
        a0y = fma2_(pp0, vxy.y, a0y);
        a0z = fma2_(pp0, vzw.x, a0z);
        a0w = fma2_(pp0, vzw.y, a0w);
        a1x = fma2_(pp1, vxy.x, a1x);
        a1y = fma2_(pp1, vxy.y, a1y);
        a1z = fma2_(pp1, vzw.x, a1z);
        a1w = fma2_(pp1, vzw.y, a1w);
        a2x = fma2_(pp2, vxy.x, a2x);
        a2y = fma2_(pp2, vxy.y, a2y);
        a2z = fma2_(pp2, vzw.x, a2z);
        a2w = fma2_(pp2, vzw.y, a2w);
    }
    float sa, sb, sc;
    {
        float lo, hi;
        upk2(sA, lo, hi); sa = lo + hi;
        upk2(sB, lo, hi); sb = lo + hi;
        upk2(sC, lo, hi); sc = lo + hi;
    }
    float e0x = 0.f, e0y = 0.f, e0z = 0.f, e0w = 0.f;
    float e1x = 0.f, e1y = 0.f, e1z = 0.f, e1w = 0.f;
    float e2x = 0.f, e2y = 0.f, e2z = 0.f, e2w = 0.f;
    if (nk & 1) {   // scalar epilogue for the odd tail key (j=0 of last pair)
        const float* Kf = (const float*)Ks;
        const float* Vf = (const float*)Vs;
        int base = (nk >> 1) * 8;
        float kx = Kf[base + 0], ky = Kf[base + 2], kz = Kf[base + 4], kw = Kf[base + 6];
        float vx = Vf[base + 0], vy = Vf[base + 2], vz = Vf[base + 4], vw = Vf[base + 6];
        float s0 = fmaf(qa.x, kx, fmaf(qa.y, ky, fmaf(qa.z, kz, qa.w * kw)));
        float s1 = fmaf(qb.x, kx, fmaf(qb.y, ky, fmaf(qb.z, kz, qb.w * kw)));
        float s2 = fmaf(qc.x, kx, fmaf(qc.y, ky, fmaf(qc.z, kz, qc.w * kw)));
        float p0 = ex2(s0), p1 = ex2(s1), p2 = ex2(s2);
        sa += p0; sb += p1; sc += p2;
        e0x = p0 * vx; e0y = p0 * vy; e0z = p0 * vz; e0w = p0 * vw;
        e1x = p1 * vx; e1y = p1 * vy; e1z = p1 * vz; e1w = p1 * vw;
        e2x = p2 * vx; e2y = p2 * vy; e2z = p2 * vz; e2w = p2 * vw;
    }
    int base = (c * NH + h) * L;
    if (q0 < L) {
        float lo, hi;
        float4 r;
        upk2(a0x, lo, hi); r.x = lo + hi + e0x;
        upk2(a0y, lo, hi); r.y = lo + hi + e0y;
        upk2(a0z, lo, hi); r.z = lo + hi + e0z;
        upk2(a0w, lo, hi); r.w = lo + hi + e0w;
        g_P[base + q0] = r;
        g_PL[base + q0] = sa;
    }
    if (q1 < L) {
        float lo, hi;
        float4 r;
        upk2(a1x, lo, hi); r.x = lo + hi + e1x;
        upk2(a1y, lo, hi); r.y = lo + hi + e1y;
        upk2(a1z, lo, hi); r.z = lo + hi + e1z;
        upk2(a1w, lo, hi); r.w = lo + hi + e1w;
        g_P[base + q1] = r;
        g_PL[base + q1] = sb;
    }
    if (q2 < L) {
        float lo, hi;
        float4 r;
        upk2(a2x, lo, hi); r.x = lo + hi + e2x;
        upk2(a2y, lo, hi); r.y = lo + hi + e2y;
        upk2(a2z, lo, hi); r.z = lo + hi + e2z;
        upk2(a2w, lo, hi); r.w = lo + hi + e2w;
        g_P[base + q2] = r;
        g_PL[base + q2] = sc;
    }
}

// ---- partial-combine + out-proj + residual + LN1: one warp per row ----
__global__ __launch_bounds__(256) void k_aoln(const float* __restrict__ w,
                                              const float* __restrict__ b,
                                              const float* __restrict__ g1,
                                              const float* __restrict__ b1) {
    __shared__ float Ws[32 * 33];
    __shared__ float Bs[32], Gs[32], B1s[32];
    for (int e = threadIdx.x; e < 1024; e += 256)
        Ws[(e >> 5) * 33 + (e & 31)] = w[e];
    if (threadIdx.x < 32) {
        Bs[threadIdx.x] = b[threadIdx.x];
        Gs[threadIdx.x] = g1[threadIdx.x];
        B1s[threadIdx.x] = b1[threadIdx.x];
    }
    __syncthreads();
    int r = (blockIdx.x * 256 + threadIdx.x) >> 5;
    int lane = threadIdx.x & 31;
    if (r >= L) return;
    // combine split-K partials: lane handles head h4, component d
    int h4 = lane >> 2, d = lane & 3;
    float o = 0.f, ls = 0.f;
#pragma unroll
    for (int c = 0; c < KSPLIT; c++) {
        int idx = (c * NH + h4) * L + r;
        o += ((const float*)g_P)[idx * 4 + d];
        ls += g_PL[idx];
    }
    float ov = o / ls;
    float acc = Bs[lane];
    const float* wr = &Ws[lane * 33];
#pragma unroll
    for (int i = 0; i < 32; i++) {
        float oi = __shfl_sync(0xffffffffu, ov, i);
        acc = fmaf(oi, wr[i], acc);
    }
    float xv = g_X[r * H + lane] + acc;
    float m = warp_sum(xv) * (1.0f / 32.0f);
    float dd = xv - m;
    float var = warp_sum(dd * dd) * (1.0f / 32.0f);
    float y = dd * rsqrtf(var + EPSF);
    g_X[r * H + lane] = fmaf(y, Gs[lane], B1s[lane]);
}

// ---- fused FF (packed f32x2): relu(X*W1^T) chunk -> W2 partial ----
// grid = (ceil(L/32), FSPL), block = 256
__global__ __launch_bounds__(256) void k_ff(const float* __restrict__ w1,
                                            const float* __restrict__ b1,
                                            const float* __restrict__ w2) {
    __shared__ float4 Xs[32 * 8];        // [r][c4]   4KB
    __shared__ float  Fs[32 * FCH];      // [r][kk]   16KB
    __shared__ float  W2s[32 * W2PAD];   // [h][kk]   16.9KB, stride 132
    int r0 = blockIdx.x * 32;
    int s  = blockIdx.y;
    {
        int r = threadIdx.x >> 3, c = threadIdx.x & 7;
        float4 v = make_float4(0.f, 0.f, 0.f, 0.f);
        if (r0 + r < L) v = ((const float4*)g_X)[(r0 + r) * 8 + c];
        Xs[threadIdx.x] = v;
    }
    int h  = threadIdx.x & 31;
    int rs = threadIdx.x >> 5;        // warp id -> row group (4 rows)
    int fl = threadIdx.x & 127;       // f column within chunk
    int rh = (threadIdx.x >> 7) * 16; // row half for ff1 stage (0 or 16)
    ull accp0 = 0, accp1 = 0, accp2 = 0, accp3 = 0;  // packed over k-parity
#pragma unroll 1
    for (int ch = 0; ch < (FF / FSPL) / FCH; ch++) {   // 2 chunks of 128 f
        int fbase = s * (FF / FSPL) + ch * FCH;
        __syncthreads();   // prev chunk's readers done; Xs ready on first iter
        {   // stage W2s[h][kk] from w2 (layout [h][ff] already!): coalesced
#pragma unroll
            for (int j = 0; j < 4; j++) {
                int t = threadIdx.x + 256 * j;
                int hh = t >> 5, k4 = (t & 31) * 4;
                *(float4*)(W2s + hh * W2PAD + k4) =
                    *(const float4*)(w2 + hh * FF + fbase + k4);
            }
        }
        {   // ff1: two threads per f column, 16 rows each; K-packed (full 32 k)
            int f = fbase + fl;
            const ulonglong2* wp = (const ulonglong2*)(w1 + f * 32);
            ulonglong2 wv[8];
#pragma unroll
            for (int j = 0; j < 8; j++) wv[j] = wp[j];
            float bias = b1[f];
            for (int rr = 0; rr < 16; rr++) {
                int r = rh + rr;
                const ulonglong2* xp = (const ulonglong2*)&Xs[r * 8];
                ull a = mul2_(xp[0].x, wv[0].x);
                a = fma2_(xp[0].y, wv[0].y, a);
#pragma unroll
                for (int j = 1; j < 8; j++) {
                    ulonglong2 xj = xp[j];
                    a = fma2_(xj.x, wv[j].x, a);
                    a = fma2_(xj.y, wv[j].y, a);
                }
                float lo, hi;
                upk2(a, lo, hi);
                Fs[r * FCH + fl] = fmaxf(lo + hi + bias, 0.f);
            }
        }
        __syncthreads();
        // ff2 partial: thread (rs,h) rows rs*4..+3, packed over kk pairs
        const ulonglong2* wrow = (const ulonglong2*)(W2s + h * W2PAD);
        const ulonglong2* f0p = (const ulonglong2*)&Fs[(rs * 4 + 0) * FCH];
        const ulonglong2* f1p = (const ulonglong2*)&Fs[(rs * 4 + 1) * FCH];
        const ulonglong2* f2p = (const ulonglong2*)&Fs[(rs * 4 + 2) * FCH];
        const ulonglong2* f3p = (const ulonglong2*)&Fs[(rs * 4 + 3) * FCH];
#pragma unroll 8
        for (int k4 = 0; k4 < FCH / 4; k4++) {
            ulonglong2 ww = wrow[k4];
            ulonglong2 f0 = f0p[k4];
            ulonglong2 f1 = f1p[k4];
            ulonglong2 f2 = f2p[k4];
            ulonglong2 f3 = f3p[k4];
            accp0 = fma2_(f0.x, ww.x, accp0);
            accp0 = fma2_(f0.y, ww.y, accp0);
            accp1 = fma2_(f1.x, ww.x, accp1);
            accp1 = fma2_(f1.y, ww.y, accp1);
            accp2 = fma2_(f2.x, ww.x, accp2);
            accp2 = fma2_(f2.y, ww.y, accp2);
            accp3 = fma2_(f3.x, ww.x, accp3);
            accp3 = fma2_(f3.y, ww.y, accp3);
        }
    }
    ull accs[4] = {accp0, accp1, accp2, accp3};
#pragma unroll
    for (int j = 0; j < 4; j++) {
        int r = r0 + rs * 4 + j;
        if (r < L) {
            float lo, hi;
            upk2(accs[j], lo, hi);
            g_Y[(s * L + r) * H + h] = lo + hi;
        }
    }
}

// ---- FF partial-combine + bias + residual + LN2 (+ optional fused qkv) ----
__device__ __forceinline__ float ln2_row(int r, int h,
                                         const float* __restrict__ b2,
                                         const float* __restrict__ g2,
                                         const float* __restrict__ b2ln) {
    float y = b2[h];
#pragma unroll
    for (int s = 0; s < FSPL; s++) y += g_Y[(s * L + r) * H + h];
    float val = g_X[r * H + h] + y;
    float m = warp_sum(val) * (1.0f / 32.0f);
    float d = val - m;
    float var = warp_sum(d * d) * (1.0f / 32.0f);
    float yn = d * rsqrtf(var + EPSF);
    float xn = fmaf(yn, g2[h], b2ln[h]);
    g_X[r * H + h] = xn;
    return xn;
}

__global__ __launch_bounds__(256) void k_ln2(const float* __restrict__ b2,
                                             const float* __restrict__ g2,
                                             const float* __restrict__ b2ln) {
    int r = (blockIdx.x * 256 + threadIdx.x) >> 5;
    int h = threadIdx.x & 31;
    if (r >= L) return;
    ln2_row(r, h, b2, g2, b2ln);
}

// ln2 of layer l fused with qkv of layer l+1
__global__ __launch_bounds__(256) void k_ln2qkv(const float* __restrict__ b2,
                                                const float* __restrict__ g2,
                                                const float* __restrict__ b2ln,
                                                const float* __restrict__ wq,
                                                const float* __restrict__ bq) {
    __shared__ float Ws[96 * 33];
    __shared__ float Bs[96];
    for (int e = threadIdx.x; e < 96 * 32; e += 256)
        Ws[(e >> 5) * 33 + (e & 31)] = wq[e];
    if (threadIdx.x < 96) Bs[threadIdx.x] = bq[threadIdx.x];
    __syncthreads();
    int r = (blockIdx.x * 256 + threadIdx.x) >> 5;
    int lane = threadIdx.x & 31;
    if (r >= L) return;
    float xn = ln2_row(r, lane, b2, g2, b2ln);
    qkv_row(xn, r, lane, Ws, Bs);
}

// ---- classifier head ----
__global__ void k_head(const float* __restrict__ cw,
                       const float* __restrict__ cb,
                       float* __restrict__ out) {
    int lane = threadIdx.x;
    float v = g_X[lane] * cw[lane];
    v = warp_sum(v);
    if (lane == 0) {
        float z = v + cb[0];
        out[0] = 1.0f / (1.0f + expf(-z));
    }
}

extern "C" void kernel_launch(void* const* d_in, const int* in_sizes, int n_in,
                              void* d_out, int out_size) {
    const float* data  = (const float*)d_in[0];
    const float* lin_w = (const float*)d_in[1];
    const float* lin_b = (const float*)d_in[2];
    const float* qkv_w = (const float*)d_in[3];
    const float* qkv_b = (const float*)d_in[4];
    const float* out_w = (const float*)d_in[5];
    const float* out_b = (const float*)d_in[6];
    const float* ln1_g = (const float*)d_in[7];
    const float* ln1_b = (const float*)d_in[8];
    const float* ff1_w = (const float*)d_in[9];
    const float* ff1_b = (const float*)d_in[10];
    const float* ff2_w = (const float*)d_in[11];
    const float* ff2_b = (const float*)d_in[12];
    const float* ln2_g = (const float*)d_in[13];
    const float* ln2_b = (const float*)d_in[14];
    const float* cls_w = (const float*)d_in[15];
    const float* cls_b = (const float*)d_in[16];
    float* out = (float*)d_out;

    k_embed<<<(L + 255) / 256, 256>>>(data, lin_w, lin_b);
    k_qkv<<<(L + 7) / 8, 256>>>(qkv_w, qkv_b);
    for (int l = 0; l < NL; l++) {
        k_attn<<<dim3((L + QT - 1) / QT, NH, KSPLIT), 128>>>();
        k_aoln<<<(L + 7) / 8, 256>>>(out_w + l * H * H, out_b + l * H,
                                     ln1_g + l * H, ln1_b + l * H);
        k_ff<<<dim3((L + 31) / 32, FSPL), 256>>>(ff1_w + l * FF * H, ff1_b + l * FF,
                                                 ff2_w + l * H * FF);
        if (l < NL - 1) {
            k_ln2qkv<<<(L + 7) / 8, 256>>>(ff2_b + l * H, ln2_g + l * H, ln2_b + l * H,
                                           qkv_w + (l + 1) * 96 * H,
                                           qkv_b + (l + 1) * 96);
        } else {
            k_ln2<<<(L + 7) / 8, 256>>>(ff2_b + l * H, ln2_g + l * H, ln2_b + l * H);
        }
    }
    k_head<<<1, 32>>>(cls_w, cls_b, out);
}

// round 16
// speedup vs baseline: 1.1152x; 1.0137x over previous
#include <cuda_runtime.h>
#include <math.h>

#define SQ   4096
#define L    4097
#define H    32
#define NH   8
#define HD   4
#define FF   2048
#define NL   6
#define EPSF 1e-5f
// 0.5 * log2(e): fold 1/sqrt(HD)=0.5 and the exp->exp2 conversion into Q
#define QSCALE 0.72134752044448170368f
#define KSPLIT 32
#define CHUNK  130          // even: pair-aligned chunks; 32*130=4160>=4097
#define PAIRS  2049         // ceil(L/2)
#define QT     384          // queries per block (3 per thread)
#define FSPL   16           // FF split factor (FF/FSPL == FCH: single chunk)
#define FCH    128          // f-chunk per smem stage
#define W2PAD  132          // W2s row stride (floats): 528B, 16B-aligned

typedef unsigned long long ull;

// ---- persistent scratch (no allocations allowed) ----
__device__ float  g_X[L * H];             // activations [L][32]
__device__ float4 g_Q[NH * L];            // [h][pos] head-major, pre-scaled by QSCALE
__device__ float  g_K2[NH * PAIRS * 8];   // pair-interleaved: [h][pair][d*2+j]
__device__ float  g_V2[NH * PAIRS * 8];
__device__ float4 g_P[KSPLIT * NH * L];   // attention partial sum(p*v) [c][h][q]
__device__ float  g_PL[KSPLIT * NH * L];  // attention partial sum(p)   [c][h][q]
__device__ float  g_Y[FSPL * L * H];      // FF partial outputs [s][r][h]

__device__ __forceinline__ float warp_sum(float v) {
#pragma unroll
    for (int o = 16; o; o >>= 1) v += __shfl_xor_sync(0xffffffffu, v, o);
    return v;
}

// ---- packed f32x2 helpers (ptxas never auto-fuses; must be PTX) ----
__device__ __forceinline__ ull pk2(float a, float b) {
    ull r;
    asm("mov.b64 %0,{%1,%2};" : "=l"(r) : "f"(a), "f"(b));
    return r;
}
__device__ __forceinline__ void upk2(ull v, float& a, float& b) {
    asm("mov.b64 {%0,%1},%2;" : "=f"(a), "=f"(b) : "l"(v));
}
__device__ __forceinline__ ull fma2_(ull a, ull b, ull c) {
    ull r;
    asm("fma.rn.f32x2 %0,%1,%2,%3;" : "=l"(r) : "l"(a), "l"(b), "l"(c));
    return r;
}
__device__ __forceinline__ ull mul2_(ull a, ull b) {
    ull r;
    asm("mul.rn.f32x2 %0,%1,%2;" : "=l"(r) : "l"(a), "l"(b));
    return r;
}
__device__ __forceinline__ ull add2_(ull a, ull b) {
    ull r;
    asm("add.rn.f32x2 %0,%1,%2;" : "=l"(r) : "l"(a), "l"(b));
    return r;
}
__device__ __forceinline__ float ex2(float x) {
    float r;
    asm("ex2.approx.f32 %0,%1;" : "=f"(r) : "f"(x));
    return r;
}

// ---- embedding: linear+relu + sinusoidal PE, CLS row = -1 ----
__global__ void k_embed(const float* __restrict__ data,
                        const float* __restrict__ lw,
                        const float* __restrict__ lb) {
    __shared__ float divs[16];
    if (threadIdx.x < 16) {
        // match JAX: f32 arg = f32(2j) * f32(-ln(10000)/32), then exp (corr. rounded)
        float arg = (float)(2 * threadIdx.x) * (float)(-0.28782313662425575);
        divs[threadIdx.x] = (float)exp((double)arg);
    }
    __syncthreads();
    int t = blockIdx.x * blockDim.x + threadIdx.x;
    if (t >= L) return;
    if (t == 0) {
#pragma unroll
        for (int h = 0; h < H; h++) g_X[h] = -1.0f;
        return;
    }
    int s = t - 1;
    float ts = data[s * 3 + 0];
    float f1 = data[s * 3 + 1];
    float f2 = data[s * 3 + 2];
    int idx = (int)(ts / 100.0f);
    float fidx = (float)idx;
#pragma unroll
    for (int j = 0; j < 16; j++) {
        float ang = fidx * divs[j];
        float sn, cs;
        sincosf(ang, &sn, &cs);
        float v0 = fmaxf(f1 * lw[4 * j + 0] + f2 * lw[4 * j + 1] + lb[2 * j], 0.f) + sn;
        float v1 = fmaxf(f1 * lw[4 * j + 2] + f2 * lw[4 * j + 3] + lb[2 * j + 1], 0.f) + cs;
        g_X[t * H + 2 * j]     = v0;
        g_X[t * H + 2 * j + 1] = v1;
    }
}

// ---- shared qkv math: one warp per row, xv = this lane's x value ----
__device__ __forceinline__ void qkv_row(float xv, int gw, int lane,
                                        const float* Ws, const float* Bs) {
    float aq = Bs[lane], ak = Bs[32 + lane], av = Bs[64 + lane];
    const float* wq = &Ws[lane * 33];
    const float* wk = &Ws[(32 + lane) * 33];
    const float* wv = &Ws[(64 + lane) * 33];
#pragma unroll
    for (int i = 0; i < 32; i++) {
        float xi = __shfl_sync(0xffffffffu, xv, i);
        aq = fmaf(xi, wq[i], aq);
        ak = fmaf(xi, wk[i], ak);
        av = fmaf(xi, wv[i], av);
    }
    int h = lane >> 2, d = lane & 3;
    ((float*)g_Q)[(h * L + gw) * 4 + d] = aq * QSCALE;
    int ob = (h * PAIRS + (gw >> 1)) * 8 + d * 2 + (gw & 1);
    g_K2[ob] = ak;
    g_V2[ob] = av;
}

// ---- QKV projection (layer 0) ----
__global__ __launch_bounds__(256) void k_qkv(const float* __restrict__ w,
                                             const float* __restrict__ b) {
    __shared__ float Ws[96 * 33];
    __shared__ float Bs[96];
    for (int e = threadIdx.x; e < 96 * 32; e += 256)
        Ws[(e >> 5) * 33 + (e & 31)] = w[e];
    if (threadIdx.x < 96) Bs[threadIdx.x] = b[threadIdx.x];
    __syncthreads();
    int gw = (blockIdx.x * 256 + threadIdx.x) >> 5;
    int lane = threadIdx.x & 31;
    if (gw >= L) return;
    qkv_row(g_X[gw * H + lane], gw, lane, Ws, Bs);
}

// ---- attention: split-K, 3 queries/thread, 2-key packed f32x2 math ----
// grid = (ceil(L/QT), NH, KSPLIT), block = 128
__global__ __launch_bounds__(128) void k_attn() {
    __shared__ float4 Ks[66 * 2], Vs[66 * 2];  // up to 65 pairs, 2 float4 each
    int h = blockIdx.y;
    int c = blockIdx.z;
    int k0 = c * CHUNK;
    int nk = min(CHUNK, L - k0);
    int np = (nk + 1) >> 1;           // pairs staged (incl. odd tail's pair)
    int p0 = k0 >> 1;                 // k0 even by construction
    const float4* srcK = (const float4*)(g_K2 + (h * PAIRS + p0) * 8);
    const float4* srcV = (const float4*)(g_V2 + (h * PAIRS + p0) * 8);
    for (int j = threadIdx.x; j < np * 2; j += 128) {
        Ks[j] = srcK[j];
        Vs[j] = srcV[j];
    }
    int q0 = blockIdx.x * QT + threadIdx.x;
    int q1 = q0 + 128;
    int q2 = q0 + 256;
    float4 qa = make_float4(0.f, 0.f, 0.f, 0.f);
    float4 qb = make_float4(0.f, 0.f, 0.f, 0.f);
    float4 qc = make_float4(0.f, 0.f, 0.f, 0.f);
    if (q0 < L) qa = g_Q[h * L + q0];
    if (q1 < L) qb = g_Q[h * L + q1];
    if (q2 < L) qc = g_Q[h * L + q2];
    ull qx0 = pk2(qa.x, qa.x), qy0 = pk2(qa.y, qa.y);
    ull qz0 = pk2(qa.z, qa.z), qw0 = pk2(qa.w, qa.w);
    ull qx1 = pk2(qb.x, qb.x), qy1 = pk2(qb.y, qb.y);
    ull qz1 = pk2(qb.z, qb.z), qw1 = pk2(qb.w, qb.w);
    ull qx2 = pk2(qc.x, qc.x), qy2 = pk2(qc.y, qc.y);
    ull qz2 = pk2(qc.z, qc.z), qw2 = pk2(qc.w, qc.w);
    ull z = 0;
    ull a0x = z, a0y = z, a0z = z, a0w = z;
    ull a1x = z, a1y = z, a1z = z, a1w = z;
    ull a2x = z, a2y = z, a2z = z, a2w = z;
    ull sA = z, sB = z, sC = z;
    __syncthreads();
    const ulonglong2* Kp = (const ulonglong2*)Ks;
    const ulonglong2* Vp = (const ulonglong2*)Vs;
    int npair = nk >> 1;
#pragma unroll 4
    for (int p = 0; p < npair; p++) {
        ulonglong2 kxy = Kp[2 * p];       // ({x0,x1},{y0,y1})
        ulonglong2 kzw = Kp[2 * p + 1];   // ({z0,z1},{w0,w1})
        ulonglong2 vxy = Vp[2 * p];
        ulonglong2 vzw = Vp[2 * p + 1];
        ull t0 = fma2_(qz0, kzw.x, mul2_(qw0, kzw.y));
        t0 = fma2_(qx0, kxy.x, fma2_(qy0, kxy.y, t0));
        ull t1 = fma2_(qz1, kzw.x, mul2_(qw1, kzw.y));
        t1 = fma2_(qx1, kxy.x, fma2_(qy1, kxy.y, t1));
        ull t2 = fma2_(qz2, kzw.x, mul2_(qw2, kzw.y));
        t2 = fma2_(qx2, kxy.x, fma2_(qy2, kxy.y, t2));
        float s0a, s0b, s1a, s1b, s2a, s2b;
        upk2(t0, s0a, s0b);
        upk2(t1, s1a, s1b);
        upk2(t2, s2a, s2b);
        float p0a = ex2(s0a), p0b = ex2(s0b);
        float p1a = ex2(s1a), p1b = ex2(s1b);
        float p2a = ex2(s2a), p2b = ex2(s2b);
        ull pp0 = pk2(p0a, p0b);
        ull pp1 = pk2(p1a, p1b);
        ull pp2 = pk2(p2a, p2b);
        sA = add2_(sA, pp0);
        sB = add2_(sB, pp1);
        sC = add2_(sC, pp2);
        a0x = fma2_(pp0, vxy.x, a0x);
        a0y = fma2_(pp0, vxy.y, a0y);
        a0z = fma2_(pp0, vzw.x, a0z);
        a0w = fma2_(pp0, vzw.y, a0w);
        a1x = fma2_(pp1, vxy.x, a1x);
        a1y = fma2_(pp1, vxy.y, a1y);
        a1z = fma2_(pp1, vzw.x, a1z);
        a1w = fma2_(pp1, vzw.y, a1w);
        a2x = fma2_(pp2, vxy.x, a2x);
        a2y = fma2_(pp2, vxy.y, a2y);
        a2z = fma2_(pp2, vzw.x, a2z);
        a2w = fma2_(pp2, vzw.y, a2w);
    }
    float sa, sb, sc;
    {
        float lo, hi;
        upk2(sA, lo, hi); sa = lo + hi;
        upk2(sB, lo, hi); sb = lo + hi;
        upk2(sC, lo, hi); sc = lo + hi;
    }
    float e0x = 0.f, e0y = 0.f, e0z = 0.f, e0w = 0.f;
    float e1x = 0.f, e1y = 0.f, e1z = 0.f, e1w = 0.f;
    float e2x = 0.f, e2y = 0.f, e2z = 0.f, e2w = 0.f;
    if (nk & 1) {   // scalar epilogue for the odd tail key (j=0 of last pair)
        const float* Kf = (const float*)Ks;
        const float* Vf = (const float*)Vs;
        int base = (nk >> 1) * 8;
        float kx = Kf[base + 0], ky = Kf[base + 2], kz = Kf[base + 4], kw = Kf[base + 6];
        float vx = Vf[base + 0], vy = Vf[base + 2], vz = Vf[base + 4], vw = Vf[base + 6];
        float s0 = fmaf(qa.x, kx, fmaf(qa.y, ky, fmaf(qa.z, kz, qa.w * kw)));
        float s1 = fmaf(qb.x, kx, fmaf(qb.y, ky, fmaf(qb.z, kz, qb.w * kw)));
        float s2 = fmaf(qc.x, kx, fmaf(qc.y, ky, fmaf(qc.z, kz, qc.w * kw)));
        float p0 = ex2(s0), p1 = ex2(s1), p2 = ex2(s2);
        sa += p0; sb += p1; sc += p2;
        e0x = p0 * vx; e0y = p0 * vy; e0z = p0 * vz; e0w = p0 * vw;
        e1x = p1 * vx; e1y = p1 * vy; e1z = p1 * vz; e1w = p1 * vw;
        e2x = p2 * vx; e2y = p2 * vy; e2z = p2 * vz; e2w = p2 * vw;
    }
    int base = (c * NH + h) * L;
    if (q0 < L) {
        float lo, hi;
        float4 r;
        upk2(a0x, lo, hi); r.x = lo + hi + e0x;
        upk2(a0y, lo, hi); r.y = lo + hi + e0y;
        upk2(a0z, lo, hi); r.z = lo + hi + e0z;
        upk2(a0w, lo, hi); r.w = lo + hi + e0w;
        g_P[base + q0] = r;
        g_PL[base + q0] = sa;
    }
    if (q1 < L) {
        float lo, hi;
        float4 r;
        upk2(a1x, lo, hi); r.x = lo + hi + e1x;
        upk2(a1y, lo, hi); r.y = lo + hi + e1y;
        upk2(a1z, lo, hi); r.z = lo + hi + e1z;
        upk2(a1w, lo, hi); r.w = lo + hi + e1w;
        g_P[base + q1] = r;
        g_PL[base + q1] = sb;
    }
    if (q2 < L) {
        float lo, hi;
        float4 r;
        upk2(a2x, lo, hi); r.x = lo + hi + e2x;
        upk2(a2y, lo, hi); r.y = lo + hi + e2y;
        upk2(a2z, lo, hi); r.z = lo + hi + e2z;
        upk2(a2w, lo, hi); r.w = lo + hi + e2w;
        g_P[base + q2] = r;
        g_PL[base + q2] = sc;
    }
}

// ---- partial-combine + out-proj + residual + LN1: one warp per row ----
__global__ __launch_bounds__(256) void k_aoln(const float* __restrict__ w,
                                              const float* __restrict__ b,
                                              const float* __restrict__ g1,
                                              const float* __restrict__ b1) {
    __shared__ float Ws[32 * 33];
    __shared__ float Bs[32], Gs[32], B1s[32];
    for (int e = threadIdx.x; e < 1024; e += 256)
        Ws[(e >> 5) * 33 + (e & 31)] = w[e];
    if (threadIdx.x < 32) {
        Bs[threadIdx.x] = b[threadIdx.x];
        Gs[threadIdx.x] = g1[threadIdx.x];
        B1s[threadIdx.x] = b1[threadIdx.x];
    }
    __syncthreads();
    int r = (blockIdx.x * 256 + threadIdx.x) >> 5;
    int lane = threadIdx.x & 31;
    if (r >= L) return;
    // combine split-K partials: lane handles head h4, component d
    int h4 = lane >> 2, d = lane & 3;
    float o = 0.f, ls = 0.f;
#pragma unroll
    for (int c = 0; c < KSPLIT; c++) {
        int idx = (c * NH + h4) * L + r;
        o += ((const float*)g_P)[idx * 4 + d];
        ls += g_PL[idx];
    }
    float ov = o / ls;
    float acc = Bs[lane];
    const float* wr = &Ws[lane * 33];
#pragma unroll
    for (int i = 0; i < 32; i++) {
        float oi = __shfl_sync(0xffffffffu, ov, i);
        acc = fmaf(oi, wr[i], acc);
    }
    float xv = g_X[r * H + lane] + acc;
    float m = warp_sum(xv) * (1.0f / 32.0f);
    float dd = xv - m;
    float var = warp_sum(dd * dd) * (1.0f / 32.0f);
    float y = dd * rsqrtf(var + EPSF);
    g_X[r * H + lane] = fmaf(y, Gs[lane], B1s[lane]);
}

// ---- fused FF (packed f32x2): relu(X*W1^T) chunk -> W2 partial ----
// grid = (ceil(L/32), FSPL), block = 256; single 128-f chunk per block
__global__ __launch_bounds__(256) void k_ff(const float* __restrict__ w1,
                                            const float* __restrict__ b1,
                                            const float* __restrict__ w2) {
    __shared__ float4 Xs[32 * 8];        // [r][c4]   4KB
    __shared__ float  Fs[32 * FCH];      // [r][kk]   16KB
    __shared__ float  W2s[32 * W2PAD];   // [h][kk]   16.9KB, stride 132
    int r0 = blockIdx.x * 32;
    int s  = blockIdx.y;
    {
        int r = threadIdx.x >> 3, c = threadIdx.x & 7;
        float4 v = make_float4(0.f, 0.f, 0.f, 0.f);
        if (r0 + r < L) v = ((const float4*)g_X)[(r0 + r) * 8 + c];
        Xs[threadIdx.x] = v;
    }
    int h  = threadIdx.x & 31;
    int rs = threadIdx.x >> 5;        // warp id -> row group (4 rows)
    int fl = threadIdx.x & 127;       // f column within chunk
    int rh = (threadIdx.x >> 7) * 16; // row half for ff1 stage (0 or 16)
    ull accp0 = 0, accp1 = 0, accp2 = 0, accp3 = 0;  // packed over k-parity
    int fbase = s * FCH;
    {   // stage W2s[h][kk] from w2 (layout [h][ff] already!): coalesced
#pragma unroll
        for (int j = 0; j < 4; j++) {
            int t = threadIdx.x + 256 * j;
            int hh = t >> 5, k4 = (t & 31) * 4;
            *(float4*)(W2s + hh * W2PAD + k4) =
                *(const float4*)(w2 + hh * FF + fbase + k4);
        }
    }
    __syncthreads();   // Xs ready (W2s readers wait on second barrier anyway)
    {   // ff1: two threads per f column, 16 rows each; K-packed (full 32 k)
        int f = fbase + fl;
        const ulonglong2* wp = (const ulonglong2*)(w1 + f * 32);
        ulonglong2 wv[8];
#pragma unroll
        for (int j = 0; j < 8; j++) wv[j] = wp[j];
        float bias = b1[f];
        for (int rr = 0; rr < 16; rr++) {
            int r = rh + rr;
            const ulonglong2* xp = (const ulonglong2*)&Xs[r * 8];
            ull a = mul2_(xp[0].x, wv[0].x);
            a = fma2_(xp[0].y, wv[0].y, a);
#pragma unroll
            for (int j = 1; j < 8; j++) {
                ulonglong2 xj = xp[j];
                a = fma2_(xj.x, wv[j].x, a);
                a = fma2_(xj.y, wv[j].y, a);
            }
            float lo, hi;
            upk2(a, lo, hi);
            Fs[r * FCH + fl] = fmaxf(lo + hi + bias, 0.f);
        }
    }
    __syncthreads();
    // ff2 partial: thread (rs,h) rows rs*4..+3, packed over kk pairs
    const ulonglong2* wrow = (const ulonglong2*)(W2s + h * W2PAD);
    const ulonglong2* f0p = (const ulonglong2*)&Fs[(rs * 4 + 0) * FCH];
    const ulonglong2* f1p = (const ulonglong2*)&Fs[(rs * 4 + 1) * FCH];
    const ulonglong2* f2p = (const ulonglong2*)&Fs[(rs * 4 + 2) * FCH];
    const ulonglong2* f3p = (const ulonglong2*)&Fs[(rs * 4 + 3) * FCH];
#pragma unroll 8
    for (int k4 = 0; k4 < FCH / 4; k4++) {
        ulonglong2 ww = wrow[k4];
        ulonglong2 f0 = f0p[k4];
        ulonglong2 f1 = f1p[k4];
        ulonglong2 f2 = f2p[k4];
        ulonglong2 f3 = f3p[k4];
        accp0 = fma2_(f0.x, ww.x, accp0);
        accp0 = fma2_(f0.y, ww.y, accp0);
        accp1 = fma2_(f1.x, ww.x, accp1);
        accp1 = fma2_(f1.y, ww.y, accp1);
        accp2 = fma2_(f2.x, ww.x, accp2);
        accp2 = fma2_(f2.y, ww.y, accp2);
        accp3 = fma2_(f3.x, ww.x, accp3);
        accp3 = fma2_(f3.y, ww.y, accp3);
    }
    ull accs[4] = {accp0, accp1, accp2, accp3};
#pragma unroll
    for (int j = 0; j < 4; j++) {
        int r = r0 + rs * 4 + j;
        if (r < L) {
            float lo, hi;
            upk2(accs[j], lo, hi);
            g_Y[(s * L + r) * H + h] = lo + hi;
        }
    }
}

// ---- FF partial-combine + bias + residual + LN2 (+ optional fused qkv) ----
__device__ __forceinline__ float ln2_row(int r, int h,
                                         const float* __restrict__ b2,
                                         const float* __restrict__ g2,
                                         const float* __restrict__ b2ln) {
    float y = b2[h];
#pragma unroll
    for (int s = 0; s < FSPL; s++) y += g_Y[(s * L + r) * H + h];
    float val = g_X[r * H + h] + y;
    float m = warp_sum(val) * (1.0f / 32.0f);
    float d = val - m;
    float var = warp_sum(d * d) * (1.0f / 32.0f);
    float yn = d * rsqrtf(var + EPSF);
    float xn = fmaf(yn, g2[h], b2ln[h]);
    g_X[r * H + h] = xn;
    return xn;
}

__global__ __launch_bounds__(256) void k_ln2(const float* __restrict__ b2,
                                             const float* __restrict__ g2,
                                             const float* __restrict__ b2ln) {
    int r = (blockIdx.x * 256 + threadIdx.x) >> 5;
    int h = threadIdx.x & 31;
    if (r >= L) return;
    ln2_row(r, h, b2, g2, b2ln);
}

// ln2 of layer l fused with qkv of layer l+1
__global__ __launch_bounds__(256) void k_ln2qkv(const float* __restrict__ b2,
                                                const float* __restrict__ g2,
                                                const float* __restrict__ b2ln,
                                                const float* __restrict__ wq,
                                                const float* __restrict__ bq) {
    __shared__ float Ws[96 * 33];
    __shared__ float Bs[96];
    for (int e = threadIdx.x; e < 96 * 32; e += 256)
        Ws[(e >> 5) * 33 + (e & 31)] = wq[e];
    if (threadIdx.x < 96) Bs[threadIdx.x] = bq[threadIdx.x];
    __syncthreads();
    int r = (blockIdx.x * 256 + threadIdx.x) >> 5;
    int lane = threadIdx.x & 31;
    if (r >= L) return;
    float xn = ln2_row(r, lane, b2, g2, b2ln);
    qkv_row(xn, r, lane, Ws, Bs);
}

// ---- classifier head ----
__global__ void k_head(const float* __restrict__ cw,
                       const float* __restrict__ cb,
                       float* __restrict__ out) {
    int lane = threadIdx.x;
    float v = g_X[lane] * cw[lane];
    v = warp_sum(v);
    if (lane == 0) {
        float z = v + cb[0];
        out[0] = 1.0f / (1.0f + expf(-z));
    }
}

extern "C" void kernel_launch(void* const* d_in, const int* in_sizes, int n_in,
                              void* d_out, int out_size) {
    const float* data  = (const float*)d_in[0];
    const float* lin_w = (const float*)d_in[1];
    const float* lin_b = (const float*)d_in[2];
    const float* qkv_w = (const float*)d_in[3];
    const float* qkv_b = (const float*)d_in[4];
    const float* out_w = (const float*)d_in[5];
    const float* out_b = (const float*)d_in[6];
    const float* ln1_g = (const float*)d_in[7];
    const float* ln1_b = (const float*)d_in[8];
    const float* ff1_w = (const float*)d_in[9];
    const float* ff1_b = (const float*)d_in[10];
    const float* ff2_w = (const float*)d_in[11];
    const float* ff2_b = (const float*)d_in[12];
    const float* ln2_g = (const float*)d_in[13];
    const float* ln2_b = (const float*)d_in[14];
    const float* cls_w = (const float*)d_in[15];
    const float* cls_b = (const float*)d_in[16];
    float* out = (float*)d_out;

    k_embed<<<(L + 255) / 256, 256>>>(data, lin_w, lin_b);
    k_qkv<<<(L + 7) / 8, 256>>>(qkv_w, qkv_b);
    for (int l = 0; l < NL; l++) {
        k_attn<<<dim3((L + QT - 1) / QT, NH, KSPLIT), 128>>>();
        k_aoln<<<(L + 7) / 8, 256>>>(out_w + l * H * H, out_b + l * H,
                                     ln1_g + l * H, ln1_b + l * H);
        k_ff<<<dim3((L + 31) / 32, FSPL), 256>>>(ff1_w + l * FF * H, ff1_b + l * FF,
                                                 ff2_w + l * H * FF);
        if (l < NL - 1) {
            k_ln2qkv<<<(L + 7) / 8, 256>>>(ff2_b + l * H, ln2_g + l * H, ln2_b + l * H,
                                           qkv_w + (l + 1) * 96 * H,
                                           qkv_b + (l + 1) * 96);
        } else {
            k_ln2<<<(L + 7) / 8, 256>>>(ff2_b + l * H, ln2_g + l * H, ln2_b + l * H);
        }
    }
    k_head<<<1, 32>>>(cls_w, cls_b, out);
}